// round 16
// baseline (speedup 1.0000x reference)
#include <cuda_runtime.h>
#include <cuda_bf16.h>
#include <math.h>
#include <stdint.h>

#define NN 16384
#define DD 64
#define KK 8
#define EE (NN*KK)
#define NT 64          // threads per knn block (2 warps)
#define RPB 64         // src rows per block group
#define NQ 4           // dst-split quarters (blocks per src group)
#define TDT 64         // dst rows per smem tile
#define MM 10          // candidates kept per src row per quarter
#define NC 10          // merged candidates per row for refine
#define CAP 10         // per-thread append buffer capacity
#define FTRIG 3        // flush trigger: cnt >= FTRIG (FTRIG <= CAP-7; 8 appends/check)
#define RR 32          // rows per refine block
#define NPART 512      // refine partial-sum blocks

#define F_INF __int_as_float(0x7f800000)
typedef unsigned long long ull;

// ---------------- device scratch (static, no allocation) ----------------
__device__ float  g_sqsF[NN];               // RN(||src||^2) via Dot2
__device__ float  g_sqdF[NN];               // RN(||dst||^2) via Dot2
__device__ __nv_bfloat16 g_srcb[NN * DD];
__device__ __nv_bfloat16 g_dstb[NN * DD];
__device__ int    g_dstStart[8];
__device__ int    g_dstEnd[8];
__device__ ull    g_cand40[NQ * MM * NN];   // [q*MM+s][i] packed (score,idx)
__device__ int    g_cand[NN * NC];
__device__ float  g_lik[EE];
__device__ float  g_wtmp[EE];
__device__ float  g_psum[NPART];
__device__ float  g_psq[NPART];
__device__ float  g_pw[NPART];

// ---------------- error-free compensated fp32 (Dot2, Ogita-Rump-Oishi) -----
__device__ __forceinline__ void dacc(float a, float b, float& s, float& comp) {
    float p = __fmul_rn(a, b);
    float e = __fmaf_rn(a, b, -p);          // exact: a*b = p + e
    float t = __fadd_rn(s, p);
    float z = __fsub_rn(t, s);
    comp = __fadd_rn(comp,
        __fadd_rn(__fadd_rn(__fsub_rn(s, __fsub_rn(t, z)), __fsub_rn(p, z)), e));
    s = t;
}
__device__ __forceinline__ float dot2_final(float s0, float c0, float s1, float c1) {
    float t = __fadd_rn(s0, s1);
    float z = __fsub_rn(t, s0);
    float e = __fadd_rn(__fsub_rn(s0, __fsub_rn(t, z)), __fsub_rn(s1, z));
    return __fadd_rn(t, __fadd_rn(__fadd_rn(c0, c1), e));
}

// ---------------- warp MMA (sm_80-era PTX; HMMA on sm_103) ----------------
#define MMA_BF16(D0, D1, D2, D3, A, B0, B1)                                   \
    asm volatile(                                                             \
        "mma.sync.aligned.m16n8k16.row.col.f32.bf16.bf16.f32 "                \
        "{%0,%1,%2,%3}, {%4,%5,%6,%7}, {%8,%9}, {%0,%1,%2,%3};"               \
        : "+f"(D0), "+f"(D1), "+f"(D2), "+f"(D3)                              \
        : "r"((A)[0]), "r"((A)[1]), "r"((A)[2]), "r"((A)[3]),                 \
          "r"(B0), "r"(B1))

// first k-step: C = 0 (no accumulator init MOVs needed)
#define MMA_BF16_INIT(D0, D1, D2, D3, A, B0, B1)                              \
    asm volatile(                                                             \
        "mma.sync.aligned.m16n8k16.row.col.f32.bf16.bf16.f32 "                \
        "{%0,%1,%2,%3}, {%4,%5,%6,%7}, {%8,%9}, {%10,%11,%12,%13};"           \
        : "=f"(D0), "=f"(D1), "=f"(D2), "=f"(D3)                              \
        : "r"((A)[0]), "r"((A)[1]), "r"((A)[2]), "r"((A)[3]),                 \
          "r"(B0), "r"(B1),                                                   \
          "f"(0.f), "f"(0.f), "f"(0.f), "f"(0.f))

__device__ __forceinline__ ull packsc(float sc, int j) {
    ull r;
    asm("mov.b64 %0, {%1, %2};" : "=l"(r) : "r"((unsigned)j), "f"(sc));
    return r;
}

#define LIST_INSERT(SC, IX) do {                                              \
    _Pragma("unroll")                                                         \
    for (int _s = 0; _s < MM; _s++)                                           \
        if (_s == fws) { tsc[_s] = (SC); tidx[_s] = (IX); }                   \
    fw = tsc[0]; fws = 0;                                                     \
    _Pragma("unroll")                                                         \
    for (int _s = 1; _s < MM; _s++)                                           \
        if (tsc[_s] > fw) { fw = tsc[_s]; fws = _s; }                         \
} while (0)

// Out-of-line flush: folds buffered items into smem top-MM list, returns new
// threshold. Called warp-uniformly; single code copy (I$ relief).
__device__ __noinline__ float flush_fn(int tid, int cnt,
                                       ull (*sbuf)[NT],
                                       float (*lsc)[NT], int (*lix)[NT]) {
    float tsc[MM]; int tidx[MM];
#pragma unroll
    for (int s = 0; s < MM; s++) { tsc[s] = lsc[s][tid]; tidx[s] = lix[s][tid]; }
    float fw = tsc[0]; int fws = 0;
#pragma unroll
    for (int s = 1; s < MM; s++)
        if (tsc[s] > fw) { fw = tsc[s]; fws = s; }
#pragma unroll 1
    for (int k = 0; k < cnt; k++) {
        ull v = sbuf[k][tid];
        float sc = __uint_as_float((unsigned)(v >> 32));
        int ix = (int)(v & 0xffffffffu);
        if (sc < fw) { LIST_INSERT(sc, ix); }
    }
#pragma unroll
    for (int s = 0; s < MM; s++) { lsc[s][tid] = tsc[s]; lix[s][tid] = tidx[s]; }
    return fw;
}

// ---------------- K0a: dst norms (Dot2 fp32) + bf16 convert ----------------
__global__ void prep_dst_kernel(const float* __restrict__ dst) {
    int j = blockIdx.x * blockDim.x + threadIdx.x;
    const float4* pd = (const float4*)(dst + (size_t)j * DD);
    __nv_bfloat162* ob = (__nv_bfloat162*)(g_dstb + (size_t)j * DD);
    float s0 = 0.f, c0 = 0.f, s1 = 0.f, c1 = 0.f;
#pragma unroll
    for (int q = 0; q < 16; q++) {
        float4 b = pd[q];
        dacc(b.x, b.x, s0, c0);
        dacc(b.y, b.y, s1, c1);
        dacc(b.z, b.z, s0, c0);
        dacc(b.w, b.w, s1, c1);
        ob[2 * q]     = __float22bfloat162_rn(make_float2(b.x, b.y));
        ob[2 * q + 1] = __float22bfloat162_rn(make_float2(b.z, b.w));
    }
    g_sqdF[j] = dot2_final(s0, c0, s1, c1);
}

// ---------------- K0b: src norms (Dot2 fp32) + bf16 convert ----------------
__global__ void prep_src_kernel(const float* __restrict__ src) {
    int j = blockIdx.x * blockDim.x + threadIdx.x;
    const float4* ps = (const float4*)(src + (size_t)j * DD);
    __nv_bfloat162* ob = (__nv_bfloat162*)(g_srcb + (size_t)j * DD);
    float s0 = 0.f, c0 = 0.f, s1 = 0.f, c1 = 0.f;
#pragma unroll
    for (int q = 0; q < 16; q++) {
        float4 a = ps[q];
        dacc(a.x, a.x, s0, c0);
        dacc(a.y, a.y, s1, c1);
        dacc(a.z, a.z, s0, c0);
        dacc(a.w, a.w, s1, c1);
        ob[2 * q]     = __float22bfloat162_rn(make_float2(a.x, a.y));
        ob[2 * q + 1] = __float22bfloat162_rn(make_float2(a.z, a.w));
    }
    g_sqsF[j] = dot2_final(s0, c0, s1, c1);
}

// ---------------- K0c: batch boundaries ----------------
__global__ void bounds_kernel(const int* __restrict__ db) {
    int j = blockIdx.x * blockDim.x + threadIdx.x;
    if (j >= NN) return;
    int b = db[j];
    if (j == 0 || db[j - 1] != b) g_dstStart[b] = j;
    if (j == NN - 1 || db[j + 1] != b) g_dstEnd[b] = j + 1;
}

// ---------------- K1: phase A — warp-MMA bf16, dst split across NQ blocks ---
__global__ __launch_bounds__(NT, 8)
void knn_mma_kernel(const int* __restrict__ sb) {
    __shared__ __align__(16) uint8_t s_b[TDT * 128];   // 8 KB swizzled bf16 tile
    __shared__ __align__(16) float s_sqdt[TDT];         // 256 B
    __shared__ __align__(16) float s_d[2][32][36];      // 9 KB D transpose
    __shared__ float s_lsc[MM][NT];                     // 2.5 KB
    __shared__ int   s_lix[MM][NT];                     // 2.5 KB
    __shared__ ull   s_buf[CAP][NT];                    // 5 KB  => 27.3 KB

    const int tid = threadIdx.x;
    const int lane = tid & 31;
    const int w = tid >> 5;                  // warp id (0,1)
    const int g = lane >> 2, t4 = lane & 3;  // mma group / thread-in-group
    const int grpId = blockIdx.x >> 2;       // src group
    const int qq = blockIdx.x & 3;           // dst quarter
    const int rowbase = grpId * RPB + w * 32;
    const int i = grpId * RPB + tid;         // this thread's src row

    // lane-constant pieces of the swizzled B-fragment addresses
    const unsigned lcOff = (unsigned)(4 * t4 + 16 * g);    // byte offset seed
    const uint8_t* rowPtr = s_b + g * 128;                 // per-lane row base

    // ---- A fragments: warp's 32 src rows x K64, canonical m16n8k16 layout
    uint32_t afr[2][4][4];
#pragma unroll
    for (int mt = 0; mt < 2; mt++)
#pragma unroll
        for (int kt = 0; kt < 4; kt++) {
            const __nv_bfloat16* a0 =
                g_srcb + (size_t)(rowbase + mt * 16 + g) * DD + kt * 16 + 2 * t4;
            const __nv_bfloat16* a1 = a0 + 8 * DD;
            afr[mt][kt][0] = *(const uint32_t*)a0;
            afr[mt][kt][1] = *(const uint32_t*)a1;
            afr[mt][kt][2] = *(const uint32_t*)(a0 + 8);
            afr[mt][kt][3] = *(const uint32_t*)(a1 + 8);
        }

    const int lo_i = g_dstStart[sb[i]];
    const int hi_i = g_dstEnd[sb[i]];
    const int lo_u = g_dstStart[sb[grpId * RPB]];
    const int hi_u = g_dstEnd[sb[grpId * RPB + RPB - 1]];
    const int lo_w = g_dstStart[sb[rowbase]];
    const int hi_w = g_dstEnd[sb[rowbase + 31]];

#pragma unroll
    for (int s = 0; s < MM; s++) { s_lsc[s][tid] = F_INF; s_lix[s][tid] = 0; }
    float thresh = F_INF;
    int cnt = 0;

#pragma unroll 1
    for (int t = qq; ; t += NQ) {
        const int tb = lo_u + t * TDT;
        if (tb >= hi_u) break;
        __syncthreads();   // previous tile's selection done
        // cooperative swizzled tile load (64 rows x 128B, 8 x uint4/thread)
#pragma unroll
        for (int u = 0; u < 8; u++) {
            int f = u * NT + tid;
            int row = f >> 3, c16 = f & 7;
            uint4 v = make_uint4(0, 0, 0, 0);
            if (tb + row < hi_u)
                v = *((const uint4*)(g_dstb + (size_t)(tb + row) * DD) + c16);
            unsigned off = (unsigned)(row * 128) + ((unsigned)(((c16 + row) & 7) * 16));
            *(uint4*)(s_b + off) = v;
        }
        s_sqdt[tid] = (tb + tid < hi_u) ? g_sqdF[tb + tid] : F_INF;
        __syncthreads();

        // warp-level skip if tile fully outside this warp's batch union
        if (tb >= hi_w || tb + TDT <= lo_w) continue;

        const bool inTile = (tb >= lo_i) && (tb + TDT <= hi_i);
        const bool fastAll = __all_sync(0xffffffffu, inTile);

#pragma unroll 1
        for (int ch = 0; ch < 2; ch++) {
            const int cb = ch * 32;
            float d[2][4][4];

#pragma unroll
            for (int kt = 0; kt < 4; kt++) {
                const unsigned o0 = (lcOff + 32u * kt) & 127u;
                const unsigned o1 = (o0 + 16u) & 127u;
#pragma unroll
                for (int n8 = 0; n8 < 4; n8++) {
                    const uint8_t* p = rowPtr + (cb + n8 * 8) * 128;
                    uint32_t b0 = *(const uint32_t*)(p + o0);
                    uint32_t b1 = *(const uint32_t*)(p + o1);
                    if (kt == 0) {
                        MMA_BF16_INIT(d[0][n8][0], d[0][n8][1], d[0][n8][2], d[0][n8][3],
                                      afr[0][kt], b0, b1);
                        MMA_BF16_INIT(d[1][n8][0], d[1][n8][1], d[1][n8][2], d[1][n8][3],
                                      afr[1][kt], b0, b1);
                    } else {
                        MMA_BF16(d[0][n8][0], d[0][n8][1], d[0][n8][2], d[0][n8][3],
                                 afr[0][kt], b0, b1);
                        MMA_BF16(d[1][n8][0], d[1][n8][1], d[1][n8][2], d[1][n8][3],
                                 afr[1][kt], b0, b1);
                    }
                }
            }

            // transpose D through smem (stride 36: conflict-free float4 reads)
            __syncwarp();
#pragma unroll
            for (int mt = 0; mt < 2; mt++)
#pragma unroll
                for (int n8 = 0; n8 < 4; n8++) {
                    const int c = n8 * 8 + 2 * t4;
                    *(float2*)&s_d[w][mt * 16 + g][c] =
                        make_float2(d[mt][n8][0], d[mt][n8][1]);
                    *(float2*)&s_d[w][mt * 16 + g + 8][c] =
                        make_float2(d[mt][n8][2], d[mt][n8][3]);
                }
            __syncwarp();

            // branchless gated selection: lane owns src row (rowbase+lane).
            // Invariant: at each flush check cnt <= FTRIG-1 (=2); between
            // checks <=8 appends -> max store index 2+7 = 9 = CAP-1. Safe.
            const float4* drow4 = (const float4*)&s_d[w][lane][0];
            const float4* sq4p = (const float4*)&s_sqdt[cb];
#pragma unroll
            for (int h2 = 0; h2 < 4; h2++) {         // flush check every 8 cand
#pragma unroll
                for (int q4 = 0; q4 < 2; q4++) {
                    const int g4 = h2 * 2 + q4;
                    const int c0 = g4 * 4;
                    float4 dv = drow4[g4];
                    float4 sq = sq4p[g4];
                    float sc0 = fmaf(-2.f, dv.x, sq.x);
                    float sc1 = fmaf(-2.f, dv.y, sq.y);
                    float sc2 = fmaf(-2.f, dv.z, sq.z);
                    float sc3 = fmaf(-2.f, dv.w, sq.w);
                    const int j0 = tb + cb + c0;
                    bool ok0 = sc0 < thresh, ok1 = sc1 < thresh;
                    bool ok2 = sc2 < thresh, ok3 = sc3 < thresh;
                    if (!fastAll) {
                        ok0 = ok0 && (j0 + 0 >= lo_i) && (j0 + 0 < hi_i);
                        ok1 = ok1 && (j0 + 1 >= lo_i) && (j0 + 1 < hi_i);
                        ok2 = ok2 && (j0 + 2 >= lo_i) && (j0 + 2 < hi_i);
                        ok3 = ok3 && (j0 + 3 >= lo_i) && (j0 + 3 < hi_i);
                    }
                    s_buf[cnt][tid] = packsc(sc0, j0 + 0); cnt += ok0;
                    s_buf[cnt][tid] = packsc(sc1, j0 + 1); cnt += ok1;
                    s_buf[cnt][tid] = packsc(sc2, j0 + 2); cnt += ok2;
                    s_buf[cnt][tid] = packsc(sc3, j0 + 3); cnt += ok3;
                }
                if (__any_sync(0xffffffffu, cnt >= FTRIG)) {
                    thresh = flush_fn(tid, cnt, s_buf, s_lsc, s_lix);
                    cnt = 0;
                }
            }
        }
    }

    thresh = flush_fn(tid, cnt, s_buf, s_lsc, s_lix);
    // coalesced packed output: slot-major layout
#pragma unroll
    for (int s = 0; s < MM; s++) {
        float sc = s_lsc[s][tid];
        int ix = s_lix[s][tid];
        if (sc == F_INF) ix = -1 - (qq * MM + s);
        g_cand40[(size_t)(qq * MM + s) * NN + i] =
            ((ull)__float_as_uint(sc) << 32) | (unsigned)(ix);
    }
}

// ---------------- K1b: merge 4 quarter lists -> top-10 per row --------------
__global__ __launch_bounds__(256)
void merge_kernel() {
    const int i = blockIdx.x * 256 + threadIdx.x;
    float tsc[NC]; int tidx[NC];
#pragma unroll
    for (int s = 0; s < NC; s++) {
        ull v = g_cand40[(size_t)s * NN + i];
        tsc[s] = __uint_as_float((unsigned)(v >> 32));
        tidx[s] = (int)(v & 0xffffffffu);
    }
    float fw = tsc[0]; int fws = 0;
#pragma unroll
    for (int s = 1; s < NC; s++)
        if (tsc[s] > fw) { fw = tsc[s]; fws = s; }
#pragma unroll 1
    for (int c = NC; c < NQ * MM; c++) {
        ull v = g_cand40[(size_t)c * NN + i];
        float sc = __uint_as_float((unsigned)(v >> 32));
        int ix = (int)(v & 0xffffffffu);
        if (sc < fw) { LIST_INSERT(sc, ix); }
    }
#pragma unroll
    for (int s = 0; s < NC; s++)
        g_cand[i * NC + s] = (tsc[s] == F_INF) ? (-1 - s) : tidx[s];
}

// ---------------- K2: phase B — Dot2 fp32 refine + ranking + partial sums ---
__global__ __launch_bounds__(RR * NC)
void refine_kernel(const float* __restrict__ src, const float* __restrict__ dst,
                   float* g0, float* g1) {
    __shared__ float sD[RR][DD + 1];      // +1 pad: kills 128B-stride bank conflicts
    __shared__ float s_sc[RR][NC];
    __shared__ int s_ix[RR][NC];
    __shared__ float redS[10], redQ[10];

    const int t = threadIdx.x;
    const int r = t / NC;
    const int c = t % NC;
    const int i0 = blockIdx.x * RR;
    const int i = i0 + r;

    for (int e = t; e < RR * DD; e += RR * NC)
        sD[e >> 6][e & 63] = src[(size_t)i0 * DD + e];
    __syncthreads();

    const int idx = g_cand[i * NC + c];
    float sc;
    float dotf = 0.f;
    if (idx >= 0) {
        const float4* dp = (const float4*)(dst + (size_t)idx * DD);
        float s0 = 0.f, c0 = 0.f, s1 = 0.f, c1 = 0.f;
#pragma unroll
        for (int q = 0; q < 16; q++) {
            float4 v = __ldg(dp + q);
            dacc(sD[r][4 * q + 0], v.x, s0, c0);
            dacc(sD[r][4 * q + 1], v.y, s1, c1);
            dacc(sD[r][4 * q + 2], v.z, s0, c0);
            dacc(sD[r][4 * q + 3], v.w, s1, c1);
        }
        dotf = dot2_final(s0, c0, s1, c1);
        // reference fp32 arithmetic: (sqs - 2*dot) + sqd, no FMA
        sc = __fadd_rn(__fadd_rn(g_sqsF[i], __fmul_rn(-2.f, dotf)), g_sqdF[idx]);
    } else {
        sc = F_INF;
    }
    s_sc[r][c] = sc;
    s_ix[r][c] = idx;
    __syncthreads();

    // stable rank: ascending (score, index) — matches jax.lax.top_k(-d2)
    int rank = 0;
#pragma unroll
    for (int m = 0; m < NC; m++) {
        float o = s_sc[r][m];
        int oi = s_ix[r][m];
        rank += (o < sc) || (o == sc && oi < idx);
    }
    const bool sel = (rank < KK) && (idx >= 0);
    if (sel) {
        int e = i * KK + rank;
        if (g0) g0[e] = (float)i;
        if (g1) g1[e] = (float)idx;
        g_lik[e] = dotf;
    }

    // block partial sums of likelihood and likelihood^2
    float v = sel ? dotf : 0.f;
    float vq = v * v;
#pragma unroll
    for (int o = 16; o > 0; o >>= 1) {
        v += __shfl_down_sync(0xffffffffu, v, o);
        vq += __shfl_down_sync(0xffffffffu, vq, o);
    }
    if ((t & 31) == 0) { redS[t >> 5] = v; redQ[t >> 5] = vq; }
    __syncthreads();
    if (t == 0) {
        float s = 0.f, q = 0.f;
#pragma unroll
        for (int u = 0; u < 10; u++) { s += redS[u]; q += redQ[u]; }
        g_psum[blockIdx.x] = s;
        g_psq[blockIdx.x] = q;
    }
}

// ---------------- K3/K4: epilogue (deterministic, 512 blocks) ----------------
__global__ void bn_kernel(const float* __restrict__ gamma,
                          const float* __restrict__ beta) {
    __shared__ float ss[256], sq[256];
    int t = threadIdx.x, b = blockIdx.x;
    ss[t] = g_psum[t] + g_psum[t + 256];
    sq[t] = g_psq[t] + g_psq[t + 256];
    __syncthreads();
    for (int off = 128; off > 0; off >>= 1) {
        if (t < off) { ss[t] += ss[t + off]; sq[t] += sq[t + off]; }
        __syncthreads();
    }
    float mean = ss[0] / (float)EE;
    float var = sq[0] / (float)EE - mean * mean;
    float a = rsqrtf(var + 1e-5f) * gamma[0];
    float c = beta[0] - mean * a;
    __syncthreads();
    int e = b * 256 + t;
    float x = g_lik[e];
    float w = 1.f / (1.f + expf(-(x * a + c)));
    g_wtmp[e] = w;
    // block partial w-sum
    ss[t] = w;
    __syncthreads();
    for (int off = 128; off > 0; off >>= 1) {
        if (t < off) ss[t] += ss[t + off];
        __syncthreads();
    }
    if (t == 0) g_pw[b] = ss[0];
}

__global__ void scale_kernel(float* wout) {
    __shared__ float ss[256];
    int t = threadIdx.x, b = blockIdx.x;
    ss[t] = g_pw[t] + g_pw[t + 256];
    __syncthreads();
    for (int off = 128; off > 0; off >>= 1) {
        if (t < off) ss[t] += ss[t + off];
        __syncthreads();
    }
    float inv = (float)EE / ss[0];
    if (!wout) return;
    int e = b * 256 + t;
    wout[e] = g_wtmp[e] * inv;
}

// ---------------- launch ----------------
extern "C" void kernel_launch(void* const* d_in, const int* in_sizes, int n_in,
                              void* d_out, int out_size) {
    const float* src = (const float*)d_in[0];
    const float* dst = (const float*)d_in[1];
    const int* sb = (const int*)d_in[2];
    const int* db = (const int*)d_in[3];
    const float* gamma = (const float*)d_in[4];
    const float* beta = (const float*)d_in[5];

    float* out = (float*)d_out;
    float* g0 = nullptr;
    float* g1 = nullptr;
    float* wout = nullptr;
    if (out_size >= 3 * EE) {
        g0 = out; g1 = out + EE; wout = out + 2 * EE;
    } else if (out_size >= 2 * EE) {
        g0 = out; g1 = out + EE;
    } else {
        wout = out;
    }

    prep_dst_kernel<<<NN / 128, 128>>>(dst);               // launch 1
    prep_src_kernel<<<NN / 128, 128>>>(src);               // launch 2
    bounds_kernel<<<NN / 128, 128>>>(db);                  // launch 3
    knn_mma_kernel<<<(NN / RPB) * NQ, NT>>>(sb);           // launch 4 (ncu slot)
    merge_kernel<<<NN / 256, 256>>>();                     // launch 5
    refine_kernel<<<NN / RR, RR * NC>>>(src, dst, g0, g1); // launch 6
    bn_kernel<<<EE / 256, 256>>>(gamma, beta);             // launch 7
    scale_kernel<<<EE / 256, 256>>>(wout);                 // launch 8
}

// round 17
// speedup vs baseline: 1.0928x; 1.0928x over previous
#include <cuda_runtime.h>
#include <cuda_bf16.h>
#include <math.h>
#include <stdint.h>

#define NN 16384
#define DD 64
#define KK 8
#define EE (NN*KK)
#define NT 64          // threads per knn block (2 warps)
#define RPB 64         // src rows per block group
#define NQ 4           // dst-split quarters (blocks per src group)
#define TDT 64         // dst rows per smem tile
#define MM 10          // candidates kept per src row per quarter
#define NC 10          // merged candidates per row for refine
#define CAP 14         // per-thread append buffer capacity (r15 optimum)
#define FTRIG 7        // flush trigger: cnt >= FTRIG (<= CAP-7; 8 appends/check)
#define RR 32          // rows per refine block
#define NPART 512      // refine partial-sum blocks

#define F_INF __int_as_float(0x7f800000)
typedef unsigned long long ull;

// ---------------- device scratch (static, no allocation) ----------------
__device__ float  g_sqsF[NN];               // RN(||src||^2) via Dot2
__device__ float  g_sqdF[NN];               // RN(||dst||^2) via Dot2
__device__ __nv_bfloat16 g_srcb[NN * DD];
__device__ __nv_bfloat16 g_dstb[NN * DD];
__device__ int    g_dstStart[8];
__device__ int    g_dstEnd[8];
__device__ ull    g_cand40[NQ * MM * NN];   // [q*MM+s][i] packed (score,idx)
__device__ int    g_cand[NN * NC];
__device__ float  g_lik[EE];
__device__ float  g_wtmp[EE];
__device__ float  g_psum[NPART];
__device__ float  g_psq[NPART];
__device__ float  g_pw[NPART];

// ---------------- error-free compensated fp32 (Dot2, Ogita-Rump-Oishi) -----
__device__ __forceinline__ void dacc(float a, float b, float& s, float& comp) {
    float p = __fmul_rn(a, b);
    float e = __fmaf_rn(a, b, -p);          // exact: a*b = p + e
    float t = __fadd_rn(s, p);
    float z = __fsub_rn(t, s);
    comp = __fadd_rn(comp,
        __fadd_rn(__fadd_rn(__fsub_rn(s, __fsub_rn(t, z)), __fsub_rn(p, z)), e));
    s = t;
}
__device__ __forceinline__ float dot2_final(float s0, float c0, float s1, float c1) {
    float t = __fadd_rn(s0, s1);
    float z = __fsub_rn(t, s0);
    float e = __fadd_rn(__fsub_rn(s0, __fsub_rn(t, z)), __fsub_rn(s1, z));
    return __fadd_rn(t, __fadd_rn(__fadd_rn(c0, c1), e));
}

// ---------------- warp MMA (sm_80-era PTX; HMMA on sm_103) ----------------
#define MMA_BF16(D0, D1, D2, D3, A, B0, B1)                                   \
    asm volatile(                                                             \
        "mma.sync.aligned.m16n8k16.row.col.f32.bf16.bf16.f32 "                \
        "{%0,%1,%2,%3}, {%4,%5,%6,%7}, {%8,%9}, {%0,%1,%2,%3};"               \
        : "+f"(D0), "+f"(D1), "+f"(D2), "+f"(D3)                              \
        : "r"((A)[0]), "r"((A)[1]), "r"((A)[2]), "r"((A)[3]),                 \
          "r"(B0), "r"(B1))

// first k-step: C = 0 (no accumulator init MOVs needed)
#define MMA_BF16_INIT(D0, D1, D2, D3, A, B0, B1)                              \
    asm volatile(                                                             \
        "mma.sync.aligned.m16n8k16.row.col.f32.bf16.bf16.f32 "                \
        "{%0,%1,%2,%3}, {%4,%5,%6,%7}, {%8,%9}, {%10,%11,%12,%13};"           \
        : "=f"(D0), "=f"(D1), "=f"(D2), "=f"(D3)                              \
        : "r"((A)[0]), "r"((A)[1]), "r"((A)[2]), "r"((A)[3]),                 \
          "r"(B0), "r"(B1),                                                   \
          "f"(0.f), "f"(0.f), "f"(0.f), "f"(0.f))

__device__ __forceinline__ ull packsc(float sc, int j) {
    ull r;
    asm("mov.b64 %0, {%1, %2};" : "=l"(r) : "r"((unsigned)j), "f"(sc));
    return r;
}

#define LIST_INSERT(SC, IX) do {                                              \
    _Pragma("unroll")                                                         \
    for (int _s = 0; _s < MM; _s++)                                           \
        if (_s == fws) { tsc[_s] = (SC); tidx[_s] = (IX); }                   \
    fw = tsc[0]; fws = 0;                                                     \
    _Pragma("unroll")                                                         \
    for (int _s = 1; _s < MM; _s++)                                           \
        if (tsc[_s] > fw) { fw = tsc[_s]; fws = _s; }                         \
} while (0)

// Out-of-line flush: folds buffered items into smem top-MM list, returns new
// threshold. Called warp-uniformly; single code copy (I$ relief).
__device__ __noinline__ float flush_fn(int tid, int cnt,
                                       ull (*sbuf)[NT],
                                       float (*lsc)[NT], int (*lix)[NT]) {
    float tsc[MM]; int tidx[MM];
#pragma unroll
    for (int s = 0; s < MM; s++) { tsc[s] = lsc[s][tid]; tidx[s] = lix[s][tid]; }
    float fw = tsc[0]; int fws = 0;
#pragma unroll
    for (int s = 1; s < MM; s++)
        if (tsc[s] > fw) { fw = tsc[s]; fws = s; }
#pragma unroll 1
    for (int k = 0; k < cnt; k++) {
        ull v = sbuf[k][tid];
        float sc = __uint_as_float((unsigned)(v >> 32));
        int ix = (int)(v & 0xffffffffu);
        if (sc < fw) { LIST_INSERT(sc, ix); }
    }
#pragma unroll
    for (int s = 0; s < MM; s++) { lsc[s][tid] = tsc[s]; lix[s][tid] = tidx[s]; }
    return fw;
}

// ---------------- K0: fused prep — norms (Dot2), bf16 convert, bounds -------
__global__ void prep_all_kernel(const float* __restrict__ src,
                                const float* __restrict__ dst,
                                const int* __restrict__ db) {
    int j = blockIdx.x * blockDim.x + threadIdx.x;
    if (j >= NN) return;
    {
        const float4* ps = (const float4*)(src + (size_t)j * DD);
        __nv_bfloat162* ob = (__nv_bfloat162*)(g_srcb + (size_t)j * DD);
        float s0 = 0.f, c0 = 0.f, s1 = 0.f, c1 = 0.f;
#pragma unroll
        for (int q = 0; q < 16; q++) {
            float4 a = ps[q];
            dacc(a.x, a.x, s0, c0);
            dacc(a.y, a.y, s1, c1);
            dacc(a.z, a.z, s0, c0);
            dacc(a.w, a.w, s1, c1);
            ob[2 * q]     = __float22bfloat162_rn(make_float2(a.x, a.y));
            ob[2 * q + 1] = __float22bfloat162_rn(make_float2(a.z, a.w));
        }
        g_sqsF[j] = dot2_final(s0, c0, s1, c1);
    }
    {
        const float4* pd = (const float4*)(dst + (size_t)j * DD);
        __nv_bfloat162* ob = (__nv_bfloat162*)(g_dstb + (size_t)j * DD);
        float s0 = 0.f, c0 = 0.f, s1 = 0.f, c1 = 0.f;
#pragma unroll
        for (int q = 0; q < 16; q++) {
            float4 b = pd[q];
            dacc(b.x, b.x, s0, c0);
            dacc(b.y, b.y, s1, c1);
            dacc(b.z, b.z, s0, c0);
            dacc(b.w, b.w, s1, c1);
            ob[2 * q]     = __float22bfloat162_rn(make_float2(b.x, b.y));
            ob[2 * q + 1] = __float22bfloat162_rn(make_float2(b.z, b.w));
        }
        g_sqdF[j] = dot2_final(s0, c0, s1, c1);
    }
    int b = db[j];
    if (j == 0 || db[j - 1] != b) g_dstStart[b] = j;
    if (j == NN - 1 || db[j + 1] != b) g_dstEnd[b] = j + 1;
}

// ---------------- K1: phase A — warp-MMA bf16, dst split across NQ blocks ---
__global__ __launch_bounds__(NT, 7)
void knn_mma_kernel(const int* __restrict__ sb) {
    __shared__ __align__(16) uint8_t s_b[TDT * 128];   // 8 KB swizzled bf16 tile
    __shared__ __align__(16) float s_sqdt[TDT];         // 256 B
    __shared__ __align__(16) float s_d[2][32][36];      // 9 KB D transpose
    __shared__ float s_lsc[MM][NT];                     // 2.5 KB
    __shared__ int   s_lix[MM][NT];                     // 2.5 KB
    __shared__ ull   s_buf[CAP][NT];                    // 7 KB  => 29.3 KB

    const int tid = threadIdx.x;
    const int lane = tid & 31;
    const int w = tid >> 5;                  // warp id (0,1)
    const int g = lane >> 2, t4 = lane & 3;  // mma group / thread-in-group
    const int grpId = blockIdx.x >> 2;       // src group
    const int qq = blockIdx.x & 3;           // dst quarter
    const int rowbase = grpId * RPB + w * 32;
    const int i = grpId * RPB + tid;         // this thread's src row

    // lane-constant pieces of the swizzled B-fragment addresses
    const unsigned lcOff = (unsigned)(4 * t4 + 16 * g);    // byte offset seed
    const uint8_t* rowPtr = s_b + g * 128;                 // per-lane row base

    // ---- A fragments: warp's 32 src rows x K64, canonical m16n8k16 layout
    uint32_t afr[2][4][4];
#pragma unroll
    for (int mt = 0; mt < 2; mt++)
#pragma unroll
        for (int kt = 0; kt < 4; kt++) {
            const __nv_bfloat16* a0 =
                g_srcb + (size_t)(rowbase + mt * 16 + g) * DD + kt * 16 + 2 * t4;
            const __nv_bfloat16* a1 = a0 + 8 * DD;
            afr[mt][kt][0] = *(const uint32_t*)a0;
            afr[mt][kt][1] = *(const uint32_t*)a1;
            afr[mt][kt][2] = *(const uint32_t*)(a0 + 8);
            afr[mt][kt][3] = *(const uint32_t*)(a1 + 8);
        }

    const int lo_i = g_dstStart[sb[i]];
    const int hi_i = g_dstEnd[sb[i]];
    const int lo_u = g_dstStart[sb[grpId * RPB]];
    const int hi_u = g_dstEnd[sb[grpId * RPB + RPB - 1]];
    const int lo_w = g_dstStart[sb[rowbase]];
    const int hi_w = g_dstEnd[sb[rowbase + 31]];

#pragma unroll
    for (int s = 0; s < MM; s++) { s_lsc[s][tid] = F_INF; s_lix[s][tid] = 0; }
    float thresh = F_INF;
    int cnt = 0;

#pragma unroll 1
    for (int t = qq; ; t += NQ) {
        const int tb = lo_u + t * TDT;
        if (tb >= hi_u) break;
        __syncthreads();   // previous tile's selection done
        // cooperative swizzled tile load (64 rows x 128B, 8 x uint4/thread)
#pragma unroll
        for (int u = 0; u < 8; u++) {
            int f = u * NT + tid;
            int row = f >> 3, c16 = f & 7;
            uint4 v = make_uint4(0, 0, 0, 0);
            if (tb + row < hi_u)
                v = *((const uint4*)(g_dstb + (size_t)(tb + row) * DD) + c16);
            unsigned off = (unsigned)(row * 128) + ((unsigned)(((c16 + row) & 7) * 16));
            *(uint4*)(s_b + off) = v;
        }
        s_sqdt[tid] = (tb + tid < hi_u) ? g_sqdF[tb + tid] : F_INF;
        __syncthreads();

        // warp-level skip if tile fully outside this warp's batch union
        if (tb >= hi_w || tb + TDT <= lo_w) continue;

        const bool inTile = (tb >= lo_i) && (tb + TDT <= hi_i);
        const bool fastAll = __all_sync(0xffffffffu, inTile);

#pragma unroll 1
        for (int ch = 0; ch < 2; ch++) {
            const int cb = ch * 32;
            float d[2][4][4];

#pragma unroll
            for (int kt = 0; kt < 4; kt++) {
                const unsigned o0 = (lcOff + 32u * kt) & 127u;
                const unsigned o1 = (o0 + 16u) & 127u;
#pragma unroll
                for (int n8 = 0; n8 < 4; n8++) {
                    const uint8_t* p = rowPtr + (cb + n8 * 8) * 128;
                    uint32_t b0 = *(const uint32_t*)(p + o0);
                    uint32_t b1 = *(const uint32_t*)(p + o1);
                    if (kt == 0) {
                        MMA_BF16_INIT(d[0][n8][0], d[0][n8][1], d[0][n8][2], d[0][n8][3],
                                      afr[0][kt], b0, b1);
                        MMA_BF16_INIT(d[1][n8][0], d[1][n8][1], d[1][n8][2], d[1][n8][3],
                                      afr[1][kt], b0, b1);
                    } else {
                        MMA_BF16(d[0][n8][0], d[0][n8][1], d[0][n8][2], d[0][n8][3],
                                 afr[0][kt], b0, b1);
                        MMA_BF16(d[1][n8][0], d[1][n8][1], d[1][n8][2], d[1][n8][3],
                                 afr[1][kt], b0, b1);
                    }
                }
            }

            // transpose D through smem (stride 36: conflict-free float4 reads)
            __syncwarp();
#pragma unroll
            for (int mt = 0; mt < 2; mt++)
#pragma unroll
                for (int n8 = 0; n8 < 4; n8++) {
                    const int c = n8 * 8 + 2 * t4;
                    *(float2*)&s_d[w][mt * 16 + g][c] =
                        make_float2(d[mt][n8][0], d[mt][n8][1]);
                    *(float2*)&s_d[w][mt * 16 + g + 8][c] =
                        make_float2(d[mt][n8][2], d[mt][n8][3]);
                }
            __syncwarp();

            // branchless gated selection: lane owns src row (rowbase+lane).
            // Invariant: at each flush check cnt <= FTRIG-1 (=6); between
            // checks <=8 appends -> max store index 6+7 = 13 = CAP-1. Safe.
            const float4* drow4 = (const float4*)&s_d[w][lane][0];
            const float4* sq4p = (const float4*)&s_sqdt[cb];
#pragma unroll
            for (int h2 = 0; h2 < 4; h2++) {         // flush check every 8 cand
#pragma unroll
                for (int q4 = 0; q4 < 2; q4++) {
                    const int g4 = h2 * 2 + q4;
                    const int c0 = g4 * 4;
                    float4 dv = drow4[g4];
                    float4 sq = sq4p[g4];
                    float sc0 = fmaf(-2.f, dv.x, sq.x);
                    float sc1 = fmaf(-2.f, dv.y, sq.y);
                    float sc2 = fmaf(-2.f, dv.z, sq.z);
                    float sc3 = fmaf(-2.f, dv.w, sq.w);
                    const int j0 = tb + cb + c0;
                    bool ok0 = sc0 < thresh, ok1 = sc1 < thresh;
                    bool ok2 = sc2 < thresh, ok3 = sc3 < thresh;
                    if (!fastAll) {
                        ok0 = ok0 && (j0 + 0 >= lo_i) && (j0 + 0 < hi_i);
                        ok1 = ok1 && (j0 + 1 >= lo_i) && (j0 + 1 < hi_i);
                        ok2 = ok2 && (j0 + 2 >= lo_i) && (j0 + 2 < hi_i);
                        ok3 = ok3 && (j0 + 3 >= lo_i) && (j0 + 3 < hi_i);
                    }
                    s_buf[cnt][tid] = packsc(sc0, j0 + 0); cnt += ok0;
                    s_buf[cnt][tid] = packsc(sc1, j0 + 1); cnt += ok1;
                    s_buf[cnt][tid] = packsc(sc2, j0 + 2); cnt += ok2;
                    s_buf[cnt][tid] = packsc(sc3, j0 + 3); cnt += ok3;
                }
                if (__any_sync(0xffffffffu, cnt >= FTRIG)) {
                    thresh = flush_fn(tid, cnt, s_buf, s_lsc, s_lix);
                    cnt = 0;
                }
            }
        }
    }

    thresh = flush_fn(tid, cnt, s_buf, s_lsc, s_lix);
    // coalesced packed output: slot-major layout
#pragma unroll
    for (int s = 0; s < MM; s++) {
        float sc = s_lsc[s][tid];
        int ix = s_lix[s][tid];
        if (sc == F_INF) ix = -1 - (qq * MM + s);
        g_cand40[(size_t)(qq * MM + s) * NN + i] =
            ((ull)__float_as_uint(sc) << 32) | (unsigned)(ix);
    }
}

// ---------------- K1b: merge 4 quarter lists -> top-10 per row --------------
__global__ __launch_bounds__(256)
void merge_kernel() {
    const int i = blockIdx.x * 256 + threadIdx.x;
    float tsc[NC]; int tidx[NC];
#pragma unroll
    for (int s = 0; s < NC; s++) {
        ull v = g_cand40[(size_t)s * NN + i];
        tsc[s] = __uint_as_float((unsigned)(v >> 32));
        tidx[s] = (int)(v & 0xffffffffu);
    }
    float fw = tsc[0]; int fws = 0;
#pragma unroll
    for (int s = 1; s < NC; s++)
        if (tsc[s] > fw) { fw = tsc[s]; fws = s; }
#pragma unroll 1
    for (int c = NC; c < NQ * MM; c++) {
        ull v = g_cand40[(size_t)c * NN + i];
        float sc = __uint_as_float((unsigned)(v >> 32));
        int ix = (int)(v & 0xffffffffu);
        if (sc < fw) { LIST_INSERT(sc, ix); }
    }
#pragma unroll
    for (int s = 0; s < NC; s++)
        g_cand[i * NC + s] = (tsc[s] == F_INF) ? (-1 - s) : tidx[s];
}

// ---------------- K2: phase B — Dot2 fp32 refine + ranking + partial sums ---
__global__ __launch_bounds__(RR * NC)
void refine_kernel(const float* __restrict__ src, const float* __restrict__ dst,
                   float* g0, float* g1) {
    __shared__ float sD[RR][DD + 1];      // +1 pad: kills 128B-stride bank conflicts
    __shared__ float s_sc[RR][NC];
    __shared__ int s_ix[RR][NC];
    __shared__ float redS[10], redQ[10];

    const int t = threadIdx.x;
    const int r = t / NC;
    const int c = t % NC;
    const int i0 = blockIdx.x * RR;
    const int i = i0 + r;

    for (int e = t; e < RR * DD; e += RR * NC)
        sD[e >> 6][e & 63] = src[(size_t)i0 * DD + e];
    __syncthreads();

    const int idx = g_cand[i * NC + c];
    float sc;
    float dotf = 0.f;
    if (idx >= 0) {
        const float4* dp = (const float4*)(dst + (size_t)idx * DD);
        float s0 = 0.f, c0 = 0.f, s1 = 0.f, c1 = 0.f;
#pragma unroll
        for (int q = 0; q < 16; q++) {
            float4 v = __ldg(dp + q);
            dacc(sD[r][4 * q + 0], v.x, s0, c0);
            dacc(sD[r][4 * q + 1], v.y, s1, c1);
            dacc(sD[r][4 * q + 2], v.z, s0, c0);
            dacc(sD[r][4 * q + 3], v.w, s1, c1);
        }
        dotf = dot2_final(s0, c0, s1, c1);
        // reference fp32 arithmetic: (sqs - 2*dot) + sqd, no FMA
        sc = __fadd_rn(__fadd_rn(g_sqsF[i], __fmul_rn(-2.f, dotf)), g_sqdF[idx]);
    } else {
        sc = F_INF;
    }
    s_sc[r][c] = sc;
    s_ix[r][c] = idx;
    __syncthreads();

    // stable rank: ascending (score, index) — matches jax.lax.top_k(-d2)
    int rank = 0;
#pragma unroll
    for (int m = 0; m < NC; m++) {
        float o = s_sc[r][m];
        int oi = s_ix[r][m];
        rank += (o < sc) || (o == sc && oi < idx);
    }
    const bool sel = (rank < KK) && (idx >= 0);
    if (sel) {
        int e = i * KK + rank;
        if (g0) g0[e] = (float)i;
        if (g1) g1[e] = (float)idx;
        g_lik[e] = dotf;
    }

    // block partial sums of likelihood and likelihood^2
    float v = sel ? dotf : 0.f;
    float vq = v * v;
#pragma unroll
    for (int o = 16; o > 0; o >>= 1) {
        v += __shfl_down_sync(0xffffffffu, v, o);
        vq += __shfl_down_sync(0xffffffffu, vq, o);
    }
    if ((t & 31) == 0) { redS[t >> 5] = v; redQ[t >> 5] = vq; }
    __syncthreads();
    if (t == 0) {
        float s = 0.f, q = 0.f;
#pragma unroll
        for (int u = 0; u < 10; u++) { s += redS[u]; q += redQ[u]; }
        g_psum[blockIdx.x] = s;
        g_psq[blockIdx.x] = q;
    }
}

// ---------------- K3/K4: epilogue (deterministic, 512 blocks) ----------------
__global__ void bn_kernel(const float* __restrict__ gamma,
                          const float* __restrict__ beta) {
    __shared__ float ss[256], sq[256];
    int t = threadIdx.x, b = blockIdx.x;
    ss[t] = g_psum[t] + g_psum[t + 256];
    sq[t] = g_psq[t] + g_psq[t + 256];
    __syncthreads();
    for (int off = 128; off > 0; off >>= 1) {
        if (t < off) { ss[t] += ss[t + off]; sq[t] += sq[t + off]; }
        __syncthreads();
    }
    float mean = ss[0] / (float)EE;
    float var = sq[0] / (float)EE - mean * mean;
    float a = rsqrtf(var + 1e-5f) * gamma[0];
    float c = beta[0] - mean * a;
    __syncthreads();
    int e = b * 256 + t;
    float x = g_lik[e];
    float w = 1.f / (1.f + expf(-(x * a + c)));
    g_wtmp[e] = w;
    ss[t] = w;
    __syncthreads();
    for (int off = 128; off > 0; off >>= 1) {
        if (t < off) ss[t] += ss[t + off];
        __syncthreads();
    }
    if (t == 0) g_pw[b] = ss[0];
}

__global__ void scale_kernel(float* wout) {
    __shared__ float ss[256];
    int t = threadIdx.x, b = blockIdx.x;
    ss[t] = g_pw[t] + g_pw[t + 256];
    __syncthreads();
    for (int off = 128; off > 0; off >>= 1) {
        if (t < off) ss[t] += ss[t + off];
        __syncthreads();
    }
    float inv = (float)EE / ss[0];
    if (!wout) return;
    int e = b * 256 + t;
    wout[e] = g_wtmp[e] * inv;
}

// ---------------- launch ----------------
extern "C" void kernel_launch(void* const* d_in, const int* in_sizes, int n_in,
                              void* d_out, int out_size) {
    const float* src = (const float*)d_in[0];
    const float* dst = (const float*)d_in[1];
    const int* sb = (const int*)d_in[2];
    const int* db = (const int*)d_in[3];
    const float* gamma = (const float*)d_in[4];
    const float* beta = (const float*)d_in[5];

    float* out = (float*)d_out;
    float* g0 = nullptr;
    float* g1 = nullptr;
    float* wout = nullptr;
    if (out_size >= 3 * EE) {
        g0 = out; g1 = out + EE; wout = out + 2 * EE;
    } else if (out_size >= 2 * EE) {
        g0 = out; g1 = out + EE;
    } else {
        wout = out;
    }

    prep_all_kernel<<<NN / 128, 128>>>(src, dst, db);      // launch 1
    knn_mma_kernel<<<(NN / RPB) * NQ, NT>>>(sb);           // launch 2
    merge_kernel<<<NN / 256, 256>>>();                     // launch 3
    refine_kernel<<<NN / RR, RR * NC>>>(src, dst, g0, g1); // launch 4 (ncu slot)
    bn_kernel<<<EE / 256, 256>>>(gamma, beta);             // launch 5
    scale_kernel<<<EE / 256, 256>>>(wout);                 // launch 6
}